// round 10
// baseline (speedup 1.0000x reference)
#include <cuda_runtime.h>
#include <cuda_bf16.h>
#include <cstdint>
#include <math.h>

#define Bb 4
#define Ii 32
#define Nn 4096
#define Dd 64
#define WP 0.5f

#define STR 68          // padded SMEM row stride (floats)
#define CQS 8           // column splits per row band
#define CT_PER 8        // 64-col tiles per block (512 cols / 8)

// ---------------- device scratch ----------------
__device__ int      g_dtype;
__device__ int      g_inst[Bb * Nn];     // original-order instance ids
__device__ int      g_cnt[Bb * Ii];
__device__ float    g_lp[Bb * Ii];
__device__ float    g_ln[Bb * Ii];
__device__ int      g_ofs[Bb * (Ii + 1)];   // instance start offsets (sorted space)
__device__ int      g_cur[Bb * (Ii + 1)];   // scatter cursors (+1 slot for unlabeled)
__device__ int      g_pos[Bb * Nn];      // original idx -> sorted pos
__device__ int      g_insts[Bb * Nn];    // sorted pos -> instance
__device__ int      g_lo[Bb * Nn];       // sorted pos -> instance range lo
__device__ int      g_hi[Bb * Nn];       // sorted pos -> instance range hi
__device__ float    g_xtf[Bb * Nn * Dd]; // tf32-rounded, instance-sorted x
__device__ float    g_te[Bb * Nn];
__device__ float    g_se[Bb * Nn];
__device__ float    g_ps[Bb * Nn];

__device__ __forceinline__ float to_tf32(float v) {
    float r;
    asm("cvt.rna.tf32.f32 %0, %1;" : "=f"(r) : "f"(v));
    return r;
}
__device__ __forceinline__ void mma8(float* d, const uint32_t* a, uint32_t b0, uint32_t b1) {
    asm volatile(
        "mma.sync.aligned.m16n8k8.row.col.f32.tf32.tf32.f32 "
        "{%0,%1,%2,%3}, {%4,%5,%6,%7}, {%8,%9}, {%0,%1,%2,%3};"
        : "+f"(d[0]), "+f"(d[1]), "+f"(d[2]), "+f"(d[3])
        : "r"(a[0]), "r"(a[1]), "r"(a[2]), "r"(a[3]), "r"(b0), "r"(b1));
}
__device__ __forceinline__ uint32_t smem_u32(const void* p) {
    return (uint32_t)__cvta_generic_to_shared(p);
}
__device__ __forceinline__ void cpasync16(uint32_t dst, const float* src) {
    asm volatile("cp.async.cg.shared.global [%0], [%1], 16;" :: "r"(dst), "l"(src));
}
#define CP_COMMIT() asm volatile("cp.async.commit_group;" ::: "memory")
#define CP_WAIT1()  asm volatile("cp.async.wait_group 1;" ::: "memory")
#define CP_WAIT0()  asm volatile("cp.async.wait_group 0;" ::: "memory")

// ---------------- kernel 1: detect label dtype + zero small scratch ----------------
__global__ void detect_kernel(const unsigned int* lab_words) {
    __shared__ int notInt, notFloat;
    int t = threadIdx.x;
    if (t == 0) { notInt = 0; notFloat = 0; }
    __syncthreads();
    int vi = 0, vf = 0;
    for (int i = t; i < 4096; i += blockDim.x) {
        unsigned int w = lab_words[i];
        if (w > 1u) vi = 1;
        if (w != 0u && w != 0x3F800000u) vf = 1;
    }
    if (vi) atomicOr(&notInt, 1);
    if (vf) atomicOr(&notFloat, 1);
    __syncthreads();
    if (t == 0) g_dtype = (!notInt) ? 1 : ((!notFloat) ? 2 : 0);
    if (t < Bb * Ii) { g_cnt[t] = 0; g_lp[t] = 0.f; g_ln[t] = 0.f; }
}

// ---------------- kernel 2: instance ids + counts ----------------
__global__ void inst_kernel(const void* lab) {
    int idx = blockIdx.x * blockDim.x + threadIdx.x;
    if (idx >= Bb * Nn) return;
    int b = idx / Nn;
    int n = idx - b * Nn;
    int dt = g_dtype;
    const unsigned char* l8  = (const unsigned char*)lab;
    const int*           l32 = (const int*)lab;
    const float*         lf  = (const float*)lab;
    int inst = -1;
    #pragma unroll 1
    for (int i = 0; i < Ii; i++) {
        size_t base = ((size_t)b * Ii + i) * Nn + n;
        bool v;
        if (dt == 0)      v = (l8[base] != 0);
        else if (dt == 1) v = (l32[base] != 0);
        else              v = (lf[base] != 0.0f);
        if (v) { inst = i; break; }
    }
    g_inst[idx] = inst;
    if (inst >= 0) atomicAdd(&g_cnt[b * Ii + inst], 1);
}

// ---------------- kernel 2b: per-batch prefix sums -> offsets & cursors ----------------
__global__ void ofs_kernel() {
    int b = threadIdx.x;            // 4 threads, serial 32-entry scan each
    if (b >= Bb) return;
    int acc = 0;
    for (int i = 0; i < Ii; i++) {
        g_ofs[b * (Ii + 1) + i] = acc;
        g_cur[b * (Ii + 1) + i] = acc;
        acc += g_cnt[b * Ii + i];
    }
    g_ofs[b * (Ii + 1) + Ii] = acc;   // labeled total; unlabeled go after
    g_cur[b * (Ii + 1) + Ii] = acc;
}

// ---------------- kernel 2c: assign sorted positions ----------------
__global__ void pos_kernel() {
    int idx = blockIdx.x * blockDim.x + threadIdx.x;
    if (idx >= Bb * Nn) return;
    int b = idx >> 12;
    int i = g_inst[idx];
    int slot = (i >= 0) ? i : Ii;
    int pos = atomicAdd(&g_cur[b * (Ii + 1) + slot], 1);
    g_pos[idx] = pos;
    int sp = b * Nn + pos;
    g_insts[sp] = i;
    g_lo[sp] = (i >= 0) ? g_ofs[b * (Ii + 1) + i] : 0;
    g_hi[sp] = (i >= 0) ? g_ofs[b * (Ii + 1) + i + 1] : 0;
}

// ---------------- kernel 2d: scatter x into sorted order (tf32) + zero stats ----------------
__global__ void copy_kernel(const float* __restrict__ x) {
    int t = blockIdx.x * blockDim.x + threadIdx.x;   // 262144 threads
    int point = t >> 4;          // b*Nn + n
    int chunk = t & 15;          // float4 chunk within row
    int b = point >> 12;
    int pos = g_pos[point];
    float4 v = *(const float4*)(x + (size_t)point * Dd + chunk * 4);
    v.x = to_tf32(v.x); v.y = to_tf32(v.y); v.z = to_tf32(v.z); v.w = to_tf32(v.w);
    *(float4*)(g_xtf + ((size_t)b * Nn + pos) * Dd + chunk * 4) = v;
    if (t < Bb * Nn) { g_te[t] = 0.f; g_se[t] = 0.f; g_ps[t] = 0.f; }
}

// ---------------- kernel 3: tf32 mma sim, sorted ranges, cp.async pipeline ----------------
__global__ __launch_bounds__(256, 2) void sim_kernel() {
    __shared__ float Bs[2][64 * STR];

    int tid = threadIdx.x;
    int wid = tid >> 5;
    int lid = tid & 31;
    int g   = lid >> 2;
    int tg  = lid & 3;

    int blk = blockIdx.x;
    int b   = blk >> 8;
    int r   = blk & 255;
    int rt  = r >> 3;
    int cq  = r & 7;
    int p0  = rt * 128;
    int c0  = cq * 512;
    const float* xb = g_xtf + (size_t)b * Nn * Dd;

    int ldr = tid >> 4;
    int cg  = tid & 15;

    // stage A (128 sorted rows) through the two B buffers, extract fragments
    #pragma unroll
    for (int h = 0; h < 2; h++)
        #pragma unroll
        for (int t = 0; t < 4; t++) {
            int row = ldr + t * 16;
            float4 v = *(const float4*)(xb + (size_t)(p0 + h * 64 + row) * Dd + cg * 4);
            *(float4*)(&Bs[h][row * STR + cg * 4]) = v;
        }
    __syncthreads();

    uint32_t af[8][4];
    {
        const float* Ab = Bs[wid >> 2];
        int rc = (wid & 3) * 16 + g;
        #pragma unroll
        for (int kk = 0; kk < 8; kk++) {
            af[kk][0] = __float_as_uint(Ab[rc * STR + kk * 8 + tg]);
            af[kk][1] = __float_as_uint(Ab[(rc + 8) * STR + kk * 8 + tg]);
            af[kk][2] = __float_as_uint(Ab[rc * STR + kk * 8 + tg + 4]);
            af[kk][3] = __float_as_uint(Ab[(rc + 8) * STR + kk * 8 + tg + 4]);
        }
    }
    __syncthreads();

    int r0g = p0 + wid * 16 + g;
    int lo0 = g_lo[b * Nn + r0g],     hi0 = g_hi[b * Nn + r0g];
    int lo1 = g_lo[b * Nn + r0g + 8], hi1 = g_hi[b * Nn + r0g + 8];
    // warp-wide row-range bounds (rows are contiguous & sorted -> one span)
    unsigned wLo = __reduce_min_sync(0xffffffffu, (unsigned)min(lo0, lo1));
    unsigned wHi = __reduce_max_sync(0xffffffffu, (unsigned)max(hi0, hi1));
    unsigned rng0 = (unsigned)(hi0 - lo0), rng1 = (unsigned)(hi1 - lo1);

    uint32_t bsm[2] = { smem_u32(&Bs[0][0]), smem_u32(&Bs[1][0]) };
    uint32_t dsto = (uint32_t)(ldr * STR + cg * 4) * 4u;

    #pragma unroll
    for (int pre = 0; pre < 2; pre++) {
        const float* src = xb + (size_t)(c0 + pre * 64) * Dd;
        #pragma unroll
        for (int t = 0; t < 4; t++)
            cpasync16(bsm[pre] + dsto + t * 16 * STR * 4, src + (size_t)(ldr + t * 16) * Dd + cg * 4);
        CP_COMMIT();
    }

    float te0 = 0.f, te1 = 0.f, se0 = 0.f, se1 = 0.f, ps0 = 0.f, ps1 = 0.f;

    #pragma unroll 1
    for (int ct = 0; ct < CT_PER; ct++) {
        int buf = ct & 1;
        if (ct == CT_PER - 1) CP_WAIT0(); else CP_WAIT1();
        __syncthreads();

        float acc[8][4];
        #pragma unroll
        for (int nt = 0; nt < 8; nt++)
            #pragma unroll
            for (int j = 0; j < 4; j++) acc[nt][j] = 0.f;

        const float* Bp = Bs[buf];
        #pragma unroll
        for (int kk = 0; kk < 8; kk++) {
            #pragma unroll
            for (int nt = 0; nt < 8; nt++) {
                int nb = nt * 8 + g;
                uint32_t b0 = __float_as_uint(Bp[nb * STR + kk * 8 + tg]);
                uint32_t b1 = __float_as_uint(Bp[nb * STR + kk * 8 + tg + 4]);
                mma8(acc[nt], af[kk], b0, b1);
            }
        }

        int tStart = c0 + ct * 64;
        bool ovl = (wLo < (unsigned)(tStart + 64)) && (wHi > (unsigned)tStart);

        if (ovl) {
            // rare path: tile intersects some row's instance range
            #pragma unroll
            for (int nt = 0; nt < 8; nt++) {
                int gc0 = tStart + nt * 8 + 2 * tg;
                float s00 = acc[nt][0], s01 = acc[nt][1];
                float s10 = acc[nt][2], s11 = acc[nt][3];
                float e00 = __expf(s00), e01 = __expf(s01);
                float e10 = __expf(s10), e11 = __expf(s11);
                te0 += e00 + e01;
                te1 += e10 + e11;
                unsigned d00 = (unsigned)(gc0 - lo0), d01 = d00 + 1;
                unsigned d10 = (unsigned)(gc0 - lo1), d11 = d10 + 1;
                if (d00 < rng0) { se0 += e00; float d = s00 - 1.f; ps0 = fmaf(d, d, ps0); }
                if (d01 < rng0) { se0 += e01; float d = s01 - 1.f; ps0 = fmaf(d, d, ps0); }
                if (d10 < rng1) { se1 += e10; float d = s10 - 1.f; ps1 = fmaf(d, d, ps1); }
                if (d11 < rng1) { se1 += e11; float d = s11 - 1.f; ps1 = fmaf(d, d, ps1); }
            }
        } else {
            // common path: te only
            #pragma unroll
            for (int nt = 0; nt < 8; nt++) {
                float e00 = __expf(acc[nt][0]), e01 = __expf(acc[nt][1]);
                float e10 = __expf(acc[nt][2]), e11 = __expf(acc[nt][3]);
                te0 += e00 + e01;
                te1 += e10 + e11;
            }
        }

        __syncthreads();
        if (ct + 2 < CT_PER) {
            const float* src = xb + (size_t)(c0 + (ct + 2) * 64) * Dd;
            #pragma unroll
            for (int t = 0; t < 4; t++)
                cpasync16(bsm[buf] + dsto + t * 16 * STR * 4, src + (size_t)(ldr + t * 16) * Dd + cg * 4);
            CP_COMMIT();
        }
    }

    #pragma unroll
    for (int off = 2; off > 0; off >>= 1) {
        te0 += __shfl_down_sync(0xffffffffu, te0, off, 4);
        te1 += __shfl_down_sync(0xffffffffu, te1, off, 4);
        se0 += __shfl_down_sync(0xffffffffu, se0, off, 4);
        se1 += __shfl_down_sync(0xffffffffu, se1, off, 4);
        ps0 += __shfl_down_sync(0xffffffffu, ps0, off, 4);
        ps1 += __shfl_down_sync(0xffffffffu, ps1, off, 4);
    }
    if (tg == 0) {
        size_t o0 = (size_t)b * Nn + r0g;
        atomicAdd(&g_te[o0], te0);
        atomicAdd(&g_se[o0], se0);
        atomicAdd(&g_ps[o0], ps0);
        atomicAdd(&g_te[o0 + 8], te1);
        atomicAdd(&g_se[o0 + 8], se1);
        atomicAdd(&g_ps[o0 + 8], ps1);
    }
}

// ---------------- kernel 4: per-row log + per-instance fold (sorted space) ----------------
__global__ void row_kernel() {
    __shared__ float s_lp[Ii];
    __shared__ float s_ln[Ii];
    int t = threadIdx.x;
    int idx = blockIdx.x * 256 + t;
    int b = idx >> 12;
    if (t < Ii) { s_lp[t] = 0.f; s_ln[t] = 0.f; }
    __syncthreads();
    int i = g_insts[idx];
    if (i >= 0) {
        atomicAdd(&s_lp[i], g_ps[idx]);
        float neg = g_te[idx] - g_se[idx];
        atomicAdd(&s_ln[i], logf(fmaxf(neg, 1e-30f)));
    }
    __syncthreads();
    if (t < Ii) {
        if (s_lp[t] != 0.f) atomicAdd(&g_lp[b * Ii + t], s_lp[t]);
        if (s_ln[t] != 0.f) atomicAdd(&g_ln[b * Ii + t], s_ln[t]);
    }
}

// ---------------- kernel 5: tiny finish ----------------
__global__ void final_kernel(float* out) {
    __shared__ float s_red[128];
    int t = threadIdx.x;
    float cnt = (float)g_cnt[t];
    float valid = (cnt >= 5.0f) ? 1.0f : 0.0f;
    float lp = g_lp[t] / fmaxf(cnt * cnt, 1.0f);
    float ln = g_ln[t] / fmaxf(cnt, 1.0f);
    s_red[t] = valid * (WP * lp + (1.0f - WP) * ln);
    __syncthreads();
    for (int off = 64; off > 0; off >>= 1) {
        if (t < off) s_red[t] += s_red[t + off];
        __syncthreads();
    }
    if (t == 0) out[0] = s_red[0] / (float)(Bb * Ii);
}

// ---------------- launch ----------------
extern "C" void kernel_launch(void* const* d_in, const int* in_sizes, int n_in,
                              void* d_out, int out_size) {
    const float* x   = (const float*)d_in[0];
    const void*  lab = d_in[1];
    float* out = (float*)d_out;

    detect_kernel<<<1, 256>>>((const unsigned int*)lab);
    inst_kernel<<<(Bb * Nn + 255) / 256, 256>>>(lab);
    ofs_kernel<<<1, 32>>>();
    pos_kernel<<<(Bb * Nn + 255) / 256, 256>>>();
    copy_kernel<<<(Bb * Nn * 16) / 256, 256>>>(x);
    sim_kernel<<<Bb * 32 * CQS, 256>>>();
    row_kernel<<<Bb * Nn / 256, 256>>>();
    final_kernel<<<1, 128>>>(out);
}